// round 6
// baseline (speedup 1.0000x reference)
#include <cuda_runtime.h>
#include <math.h>

#define N_MOL  2048
#define P_PRO  2048
#define HID    64
#define HEADS  16
#define NGRAPH 64
#define NB     256
#define NBLK   128          // 16 heads x 8 groups
#define NTHR   256
#define CHUNK  256          // query atoms per stage-3 block

// ---- global scratch (no allocation allowed) ----
__device__ float2 g_mol2[HEADS][N_MOL];     // (a_mol, exp(a_mol))
__device__ float2 g_pro2[HEADS][P_PRO];     // (a_pro, exp(a_pro))
__device__ float2 g_VE[HEADS][P_PRO];       // bin-grouped (value, exp)
__device__ int    g_binStartG[HEADS][NB + 4];
__device__ float  g_prefExpG[HEADS][NB];
__device__ float  g_sufValG[HEADS][NB + 4];
__device__ float  g_mnvG[HEADS], g_invG[HEADS];
__device__ float  g_part[HEADS][8][NGRAPH]; // per-(head,chunk) graph partials
__device__ int    g_prodA[HEADS];           // producers done (self-reset)
__device__ int    g_structGen[HEADS];       // monotone generation per head
__device__ int    g_doneCnt;                // stage-3 completions (self-reset)

struct Smem {
    float2 VE[P_PRO];        // 16KB  bin-grouped (v, e^v)
    float  rA[P_PRO];        // 8KB   raw values / detection words / final ys
    float  rE[P_PRO];        // 8KB   raw exps
    int    binStart[NB + 1];
    float  prefExp[NB];
    float  sufVal[NB + 1];
    float  yloc[CHUNK];
    int    bsc[CHUNK];
    int    hist[NB];
    int    cnt[NB];
    float  Wc[2 * HID];
    int    iwarp[8];
    double dE[8], dV[8];
    float  redmn[8], redmx[8];
    float  mnv, invv;
    int    flag;
};

__device__ __forceinline__ int bin_of(float v, float mn, float inv) {
    // no-FMA-contraction form so all call sites compute identically
    int b = (int)(__fmul_rn(__fsub_rn(v, mn), inv));
    return b < 0 ? 0 : (b > NB - 1 ? NB - 1 : b);
}

__global__ __launch_bounds__(NTHR, 1)
void fused_kernel(const float* __restrict__ mol,
                  const float* __restrict__ pro,
                  const float* __restrict__ Wmu,
                  const float* __restrict__ bmu,
                  const float* __restrict__ W1,
                  const float* __restrict__ b1,
                  const float* __restrict__ W2,
                  const float* __restrict__ b2,
                  const int*   __restrict__ batch32,
                  float* __restrict__ out) {
    __shared__ Smem sm;
    int tid  = threadIdx.x;
    int lane = tid & 31;
    int wrp  = tid >> 5;
    int h    = blockIdx.x & 15;
    int g    = blockIdx.x >> 4;

    // snapshot structure generation BEFORE any work (prev-replay value; bump
    // for this replay is causally after our own Phase-A completion)
    int s0 = *(volatile int*)&g_structGen[h];

    // ===== Phase A: block (h,g) projects 512 rows for head h, stores (a, e^a) =====
    if (tid < 2 * HID) sm.Wc[tid] = Wmu[tid * HEADS + h];
    __syncthreads();
    {
        bool is_mol = (g < 4);
        int  quad   = tid & 3;
        int  rloc   = tid >> 2;
        const float* srcbase = is_mol ? mol : pro;
        int  rowoff = is_mol ? g * 512 : (g - 4) * 512;
        const float* wseg = sm.Wc + quad * 16 + (is_mol ? 0 : HID);
        float bias = is_mol ? bmu[h] : 0.0f;
        float2* dst = is_mol ? g_mol2[h] : g_pro2[h];
#pragma unroll 1
        for (int p = 0; p < 8; p++) {
            int r = rowoff + p * 64 + rloc;
            const float* src = srcbase + r * HID + quad * 16;
            float acc = 0.0f;
#pragma unroll
            for (int q = 0; q < 4; q++) {
                float4 v = *(const float4*)(src + 4 * q);
                acc += v.x * wseg[4*q] + v.y * wseg[4*q+1]
                     + v.z * wseg[4*q+2] + v.w * wseg[4*q+3];
            }
            acc += __shfl_xor_sync(0xffffffffu, acc, 1);
            acc += __shfl_xor_sync(0xffffffffu, acc, 2);
            if (quad == 0) {
                float a = acc + bias;
                dst[r] = make_float2(a, expf(a));
            }
        }
    }
    __threadfence();
    __syncthreads();
    if (tid == 0) atomicAdd(&g_prodA[h], 1);

    if (g == 0) {
        // ===== Stage 2: structure block builds bin structure for head h =====
        if (tid == 0) {
            while (*(volatile int*)&g_prodA[h] < 8) {}
            atomicExch(&g_prodA[h], 0);     // reset for next replay
            __threadfence();
        }
        __syncthreads();

        float mn = 1e30f, mx = -1e30f;
        for (int i = tid; i < P_PRO; i += NTHR) {
            float2 ae = g_pro2[h][i];
            sm.rA[i] = ae.x; sm.rE[i] = ae.y;
            mn = fminf(mn, ae.x); mx = fmaxf(mx, ae.x);
        }
        sm.hist[tid] = 0;
        sm.cnt[tid]  = 0;
#pragma unroll
        for (int o = 16; o > 0; o >>= 1) {
            mn = fminf(mn, __shfl_xor_sync(0xffffffffu, mn, o));
            mx = fmaxf(mx, __shfl_xor_sync(0xffffffffu, mx, o));
        }
        if (lane == 0) { sm.redmn[wrp] = mn; sm.redmx[wrp] = mx; }
        __syncthreads();
        if (tid == 0) {
            float a = sm.redmn[0], b = sm.redmx[0];
#pragma unroll
            for (int i = 1; i < NTHR / 32; i++) {
                a = fminf(a, sm.redmn[i]); b = fmaxf(b, sm.redmx[i]);
            }
            sm.mnv  = a;
            sm.invv = (b > a) ? (float)NB / (b - a) : 0.0f;
        }
        __syncthreads();
        float mnv = sm.mnv, inv = sm.invv;

        // histogram (warp-aggregated: one atomic per distinct bin per warp-step)
        for (int i = tid; i < P_PRO; i += NTHR) {
            int b = bin_of(sm.rA[i], mnv, inv);
            unsigned m = __match_any_sync(0xffffffffu, b);
            if (lane == __ffs(m) - 1) atomicAdd(&sm.hist[b], __popc(m));
        }
        __syncthreads();

        // exclusive scan of hist -> binStart (warp-shfl hierarchical)
        int myCnt, myIncl;
        {
            myCnt = sm.hist[tid];
            int s = myCnt;
#pragma unroll
            for (int o = 1; o < 32; o <<= 1) {
                int t = __shfl_up_sync(0xffffffffu, s, o);
                if (lane >= o) s += t;
            }
            if (lane == 31) sm.iwarp[wrp] = s;
            __syncthreads();
            if (tid < 8) {
                int p = sm.iwarp[tid];
#pragma unroll
                for (int o = 1; o < 8; o <<= 1) {
                    int t = __shfl_up_sync(0xffu, p, o);
                    if (tid >= o) p += t;
                }
                sm.iwarp[tid] = p;
            }
            __syncthreads();
            myIncl = s + (wrp > 0 ? sm.iwarp[wrp - 1] : 0);
            sm.binStart[tid + 1] = myIncl;
            if (tid == 0) sm.binStart[0] = 0;
        }
        __syncthreads();

        // scatter into bins (warp-aggregated rank, one atomic per distinct bin)
        for (int i = tid; i < P_PRO; i += NTHR) {
            float v = sm.rA[i], e = sm.rE[i];
            int b = bin_of(v, mnv, inv);
            unsigned m = __match_any_sync(0xffffffffu, b);
            int ldr = __ffs(m) - 1;
            int rk  = __popc(m & ((1u << lane) - 1u));
            int base;
            if (lane == ldr) base = atomicAdd(&sm.cnt[b], __popc(m));
            base = __shfl_sync(0xffffffffu, base, ldr);
            sm.VE[sm.binStart[b] + base + rk] = make_float2(v, e);
        }
        __syncthreads();

        // per-bin sums + joint double scan (prefExp exclusive / sufVal suffix)
        {
            int s0b = myIncl - myCnt, e0b = myIncl;
            float fe = 0.0f, fv = 0.0f;
            for (int i = s0b; i < e0b; i++) {
                float2 ve = sm.VE[i];
                fe += ve.y; fv += ve.x;
            }
            double se = (double)fe, sv = (double)fv;
            double ise = se, isv = sv;
#pragma unroll
            for (int o = 1; o < 32; o <<= 1) {
                double te = __shfl_up_sync(0xffffffffu, ise, o);
                double tv = __shfl_up_sync(0xffffffffu, isv, o);
                if (lane >= o) { ise += te; isv += tv; }
            }
            if (lane == 31) { sm.dE[wrp] = ise; sm.dV[wrp] = isv; }
            __syncthreads();
            if (tid < 8) {
                double pe = sm.dE[tid], pv = sm.dV[tid];
#pragma unroll
                for (int o = 1; o < 8; o <<= 1) {
                    double te = __shfl_up_sync(0xffu, pe, o);
                    double tv = __shfl_up_sync(0xffu, pv, o);
                    if (tid >= o) { pe += te; pv += tv; }
                }
                sm.dE[tid] = pe; sm.dV[tid] = pv;
            }
            __syncthreads();
            double offE = (wrp > 0) ? sm.dE[wrp - 1] : 0.0;
            double offV = (wrp > 0) ? sm.dV[wrp - 1] : 0.0;
            double inclE = ise + offE, inclV = isv + offV;
            double totalV = sm.dV[7];
            sm.prefExp[tid] = (float)(inclE - se);
            sm.sufVal[tid]  = (float)(totalV - (inclV - sv));
            if (tid == 0) sm.sufVal[NB] = 0.0f;
        }
        __syncthreads();

        // publish structure to global for sibling query blocks
        for (int i = tid; i < P_PRO; i += NTHR) g_VE[h][i] = sm.VE[i];
        for (int i = tid; i <= NB; i += NTHR) {
            g_binStartG[h][i] = sm.binStart[i];
            g_sufValG[h][i]   = sm.sufVal[i];
        }
        g_prefExpG[h][tid] = sm.prefExp[tid];
        if (tid == 0) { g_mnvG[h] = mnv; g_invG[h] = inv; }
        __threadfence();
        __syncthreads();
        if (tid == 0) atomicAdd(&g_structGen[h], 1);
    } else {
        // ===== wait for structure, copy into smem =====
        if (tid == 0) {
            while (*(volatile int*)&g_structGen[h] == s0) {}
            __threadfence();
        }
        __syncthreads();
        for (int i = tid; i < P_PRO; i += NTHR) sm.VE[i] = g_VE[h][i];
        for (int i = tid; i <= NB; i += NTHR) {
            sm.binStart[i] = g_binStartG[h][i];
            sm.sufVal[i]   = g_sufValG[h][i];
        }
        sm.prefExp[tid] = g_prefExpG[h][tid];
        if (tid == 0) { sm.mnv = g_mnvG[h]; sm.invv = g_invG[h]; }
        __syncthreads();
    }

    // ===== Stage 3: 256 queries for atoms [256g, 256g+256) of head h =====
    {
        // batch dtype detection (int64 word stream is non-monotone) + chunk extract
        int* w = (int*)sm.rA;   // rA dead in both paths
        for (int i = tid; i < N_MOL; i += NTHR) w[i] = batch32[i];
        if (tid == 0) sm.flag = 0;
        __syncthreads();
        for (int i = tid; i < N_MOL - 1; i += NTHR)
            if (w[i] > w[i + 1]) sm.flag = 1;
        __syncthreads();
        int base = g * CHUNK;
        sm.bsc[tid] = sm.flag ? batch32[2 * (base + tid)] : w[base + tid];

        float mnv = sm.mnv, inv = sm.invv;
        int n = base + tid;
        float2 ae = g_mol2[h][n];
        float am = ae.x, eam = ae.y, t = -am;
        int b  = bin_of(t, mnv, inv);
        int s  = sm.binStart[b], e = sm.binStart[b + 1];
        float acc = eam * sm.prefExp[b] + sm.sufVal[b + 1]
                  + (float)(P_PRO - e) * (am + 1.0f);
        for (int i = s; i < e; i++) {
            float2 ve = sm.VE[i];
            acc += (ve.x <= t) ? eam * ve.y : (am + 1.0f + ve.x);
        }
        sm.yloc[tid] = acc;
        __syncthreads();

        // per-graph partials: 4 threads per graph (deterministic quarter split)
        int bb = tid >> 2, q = tid & 3;
        int lo = 0, hi = CHUNK;
        while (lo < hi) { int m = (lo + hi) >> 1; if (sm.bsc[m] < bb) lo = m + 1; else hi = m; }
        int lo2 = lo;
        int l2 = lo, h2 = CHUNK;
        while (l2 < h2) { int m = (l2 + h2) >> 1; if (sm.bsc[m] < bb + 1) l2 = m + 1; else h2 = m; }
        int span = l2 - lo2;
        int qlo = lo2 + ((span * q) >> 2);
        int qhi = lo2 + ((span * (q + 1)) >> 2);
        float p = 0.0f;
        for (int i = qlo; i < qhi; i++) p += sm.yloc[i];
        p += __shfl_xor_sync(0xffffffffu, p, 1);
        p += __shfl_xor_sync(0xffffffffu, p, 2);
        if (q == 0) g_part[h][g][bb] = p;
    }
    __threadfence();
    __syncthreads();
    if (tid == 0) atomicAdd(&g_doneCnt, 1);

    if (h != 0 || g != 0) return;

    // ===== Stage 4: reduce partials + MLP (block (0,0)) =====
    if (tid == 0) {
        while (*(volatile int*)&g_doneCnt < NBLK) {}
        atomicExch(&g_doneCnt, 0);           // reset for next replay
        __threadfence();
    }
    __syncthreads();
    float* ysF = sm.rA;                      // [b*16+h], 1024 floats
    for (int p2 = tid; p2 < NGRAPH * HEADS; p2 += NTHR) {
        int b = p2 >> 4, hh = p2 & 15;
        float s = 0.0f;
#pragma unroll
        for (int gg = 0; gg < 8; gg++) s += g_part[hh][gg][b];
        ysF[p2] = s * 0.001f;
    }
    __syncthreads();
    if (tid < NGRAPH) {
        float ys[HEADS];
#pragma unroll
        for (int hh = 0; hh < HEADS; hh++) ys[hh] = ysF[tid * HEADS + hh];
        float o = b2[0];
#pragma unroll
        for (int j = 0; j < 2 * HEADS; j++) {
            float a = b1[j];
#pragma unroll
            for (int hh = 0; hh < HEADS; hh++)
                a += ys[hh] * W1[hh * (2 * HEADS) + j];
            float el = (a > 0.0f) ? a : (expf(a) - 1.0f);
            o += el * W2[j];
        }
        out[tid] = o;
    }
}

// Inputs (metadata order):
// 0 mol_feats [2048,64] f32   1 fused_feats [2048,64] f32
// 2 Wmu [128,16] f32          3 bmu [16] f32
// 4 W1 [16,32] f32            5 b1 [32] f32
// 6 W2 [32,1] f32             7 b2 [1] f32
// 8 mol_batch [2048] int64-or-int32   9 num_graphs (static B=64)
extern "C" void kernel_launch(void* const* d_in, const int* in_sizes, int n_in,
                              void* d_out, int out_size) {
    fused_kernel<<<NBLK, NTHR>>>(
        (const float*)d_in[0], (const float*)d_in[1],
        (const float*)d_in[2], (const float*)d_in[3],
        (const float*)d_in[4], (const float*)d_in[5],
        (const float*)d_in[6], (const float*)d_in[7],
        (const int*)d_in[8], (float*)d_out);
}

// round 7
// speedup vs baseline: 1.4311x; 1.4311x over previous
#include <cuda_runtime.h>
#include <math.h>

#define N_MOL  2048
#define P_PRO  2048
#define HID    64
#define HEADS  16
#define NGRAPH 64
#define NB     256
#define NBLK   64           // 64 blocks x 1024 threads; blocks 0..15 are consumers
#define NTHR   1024

// ---- global scratch (no allocation allowed) ----
__device__ float2 g_mol2[HEADS][N_MOL];   // (a_mol, exp(a_mol))
__device__ float2 g_pro2[HEADS][P_PRO];   // (a_pro, exp(a_pro))
__device__ float  g_ys[NGRAPH * HEADS];
__device__ int    g_gen;                  // barrier generation (monotone)
__device__ int    g_count;                // barrier arrivals (self-resets)
__device__ int    g_done;                 // consumer completions (self-resets)

struct SA {                                // Phase A (24.6KB)
    float rows[64 * HID];                  // 64 rows x 64 feats
    float Ws[1024];                        // this half's weights [64][16]
    float trans[HEADS][65];                // padded transpose of results
};
struct SB {                                // Phase B (46.5KB)
    float2 VE[P_PRO];                      // bin-grouped (v, e^v)
    float  rA[P_PRO];                      // raw a -> later y_atom
    float  rE[P_PRO];                      // raw e^a -> later ysF
    int    bs[N_MOL];
    int    binStart[NB + 1];
    float  prefExp[NB];
    float  sufVal[NB + 1];
    int    hist[NB];
    int    cnt[NB];
    float  redmn[32], redmx[32];
    int    iwarp[8];
    double dE[8], dV[8];
    float  mnv, invv;
    int    flag;
};
union SmemU { SA a; SB b; };

__device__ __forceinline__ int bin_of(float v, float mn, float inv) {
    int b = (int)(__fmul_rn(__fsub_rn(v, mn), inv));
    return b < 0 ? 0 : (b > NB - 1 ? NB - 1 : b);
}

__global__ __launch_bounds__(NTHR, 1)
void fused_kernel(const float* __restrict__ mol,
                  const float* __restrict__ pro,
                  const float* __restrict__ Wmu,
                  const float* __restrict__ bmu,
                  const float* __restrict__ W1,
                  const float* __restrict__ b1,
                  const float* __restrict__ W2,
                  const float* __restrict__ b2,
                  const int*   __restrict__ batch32,
                  float* __restrict__ out) {
    __shared__ SmemU sm;
    int tid  = threadIdx.x;
    int lane = tid & 31;
    int wrp  = tid >> 5;
    int bid  = blockIdx.x;

    // ===== Phase A: block bid projects 64 rows (all heads), one (row,head)/thread =====
    bool is_mol  = bid < 32;
    int  rowbase = (bid & 31) * 64;
    const float* srcbase = is_mol ? mol : pro;
    sm.a.Ws[tid] = Wmu[(is_mol ? 0 : 1024) + tid];
    ((float4*)sm.a.rows)[tid] = ((const float4*)(srcbase + rowbase * HID))[tid];
    __syncthreads();
    {
        int r = tid >> 4, h = tid & 15;
        float acc = is_mol ? bmu[h] : 0.0f;
#pragma unroll
        for (int k = 0; k < HID; k++)
            acc += sm.a.rows[r * HID + k] * sm.a.Ws[k * HEADS + h];
        sm.a.trans[h][r] = acc;
    }
    __syncthreads();
    {   // coalesced float2 writeout: 64 consecutive rows per 64-thread group
        int h2 = tid >> 6, r2 = tid & 63;
        float a = sm.a.trans[h2][r2];
        float2* dst = is_mol ? g_mol2[h2] : g_pro2[h2];
        dst[rowbase + r2] = make_float2(a, expf(a));
    }
    __threadfence();
    __syncthreads();

    // ===== single global barrier; only consumer blocks (0..15) spin =====
    if (tid == 0) {
        int my = *(volatile int*)&g_gen;
        if (atomicAdd(&g_count, 1) == NBLK - 1) {
            atomicExch(&g_count, 0);
            __threadfence();
            atomicAdd(&g_gen, 1);
        } else if (bid < HEADS) {
            while (*(volatile int*)&g_gen == my) {}
        }
        __threadfence();
    }
    __syncthreads();
    if (bid >= HEADS) return;

    // ===== Phase B: head h = bid, 32 warps =====
    int h = bid;

    float mn = 1e30f, mx = -1e30f;
    for (int i = tid; i < P_PRO; i += NTHR) {   // 2 iters
        float2 ae = g_pro2[h][i];
        sm.b.rA[i] = ae.x;
        sm.b.rE[i] = ae.y;
        mn = fminf(mn, ae.x); mx = fmaxf(mx, ae.x);
    }
    for (int i = tid; i < N_MOL; i += NTHR) sm.b.bs[i] = batch32[i];
    if (tid < NB) { sm.b.hist[tid] = 0; sm.b.cnt[tid] = 0; }
    if (tid == 0) sm.b.flag = 0;
#pragma unroll
    for (int o = 16; o > 0; o >>= 1) {
        mn = fminf(mn, __shfl_xor_sync(0xffffffffu, mn, o));
        mx = fmaxf(mx, __shfl_xor_sync(0xffffffffu, mx, o));
    }
    if (lane == 0) { sm.b.redmn[wrp] = mn; sm.b.redmx[wrp] = mx; }
    __syncthreads();
    if (wrp == 0) {
        float a = sm.b.redmn[lane], b = sm.b.redmx[lane];
#pragma unroll
        for (int o = 16; o > 0; o >>= 1) {
            a = fminf(a, __shfl_xor_sync(0xffffffffu, a, o));
            b = fmaxf(b, __shfl_xor_sync(0xffffffffu, b, o));
        }
        if (lane == 0) {
            sm.b.mnv  = a;
            sm.b.invv = (b > a) ? (float)NB / (b - a) : 0.0f;
        }
    }
    // int64 detection: sorted int32 word stream is monotone; int64's is not
    for (int i = tid; i < N_MOL - 1; i += NTHR)
        if (sm.b.bs[i] > sm.b.bs[i + 1]) sm.b.flag = 1;
    __syncthreads();
    if (sm.b.flag) {   // int64: low word of each element
        for (int i = tid; i < N_MOL; i += NTHR) sm.b.bs[i] = batch32[2 * i];
    }
    float mnv = sm.b.mnv, inv = sm.b.invv;

    // histogram (2 elements/thread)
    for (int i = tid; i < P_PRO; i += NTHR)
        atomicAdd(&sm.b.hist[bin_of(sm.b.rA[i], mnv, inv)], 1);
    __syncthreads();

    // exclusive scan of hist -> binStart (threads < 256, warp-shfl hierarchical)
    int myCnt = 0, myIncl = 0;
    {
        int s = 0;
        if (tid < NB) {
            myCnt = sm.b.hist[tid];
            s = myCnt;
#pragma unroll
            for (int o = 1; o < 32; o <<= 1) {
                int t = __shfl_up_sync(0xffffffffu, s, o);
                if (lane >= o) s += t;
            }
            if (lane == 31) sm.b.iwarp[wrp] = s;
        }
        __syncthreads();
        if (tid < 8) {
            int p = sm.b.iwarp[tid];
#pragma unroll
            for (int o = 1; o < 8; o <<= 1) {
                int t = __shfl_up_sync(0xffu, p, o);
                if (tid >= o) p += t;
            }
            sm.b.iwarp[tid] = p;
        }
        __syncthreads();
        if (tid < NB) {
            myIncl = s + (wrp > 0 ? sm.b.iwarp[wrp - 1] : 0);
            sm.b.binStart[tid + 1] = myIncl;
            if (tid == 0) sm.b.binStart[0] = 0;
        }
    }
    __syncthreads();

    // scatter into bins (2 elements/thread)
    for (int i = tid; i < P_PRO; i += NTHR) {
        float v = sm.b.rA[i], e = sm.b.rE[i];
        int b = bin_of(v, mnv, inv);
        int pos = sm.b.binStart[b] + atomicAdd(&sm.b.cnt[b], 1);
        sm.b.VE[pos] = make_float2(v, e);
    }
    __syncthreads();

    // per-bin sums + joint double scan (prefExp exclusive / sufVal suffix)
    {
        double se = 0.0, sv = 0.0;
        double ise, isv;
        if (tid < NB) {
            int s0 = myIncl - myCnt, e0 = myIncl;
            float fe = 0.0f, fv = 0.0f;
            for (int i = s0; i < e0; i++) {
                float2 ve = sm.b.VE[i];
                fe += ve.y; fv += ve.x;
            }
            se = (double)fe; sv = (double)fv;
        }
        ise = se; isv = sv;
        if (tid < NB) {
#pragma unroll
            for (int o = 1; o < 32; o <<= 1) {
                double te = __shfl_up_sync(0xffffffffu, ise, o);
                double tv = __shfl_up_sync(0xffffffffu, isv, o);
                if (lane >= o) { ise += te; isv += tv; }
            }
            if (lane == 31) { sm.b.dE[wrp] = ise; sm.b.dV[wrp] = isv; }
        }
        __syncthreads();
        if (tid < 8) {
            double pe = sm.b.dE[tid], pv = sm.b.dV[tid];
#pragma unroll
            for (int o = 1; o < 8; o <<= 1) {
                double te = __shfl_up_sync(0xffu, pe, o);
                double tv = __shfl_up_sync(0xffu, pv, o);
                if (tid >= o) { pe += te; pv += tv; }
            }
            sm.b.dE[tid] = pe; sm.b.dV[tid] = pv;
        }
        __syncthreads();
        if (tid < NB) {
            double offE = (wrp > 0) ? sm.b.dE[wrp - 1] : 0.0;
            double offV = (wrp > 0) ? sm.b.dV[wrp - 1] : 0.0;
            double inclE = ise + offE, inclV = isv + offV;
            double totalV = sm.b.dV[7];
            sm.b.prefExp[tid] = (float)(inclE - se);
            sm.b.sufVal[tid]  = (float)(totalV - (inclV - sv));
            if (tid == 0) sm.b.sufVal[NB] = 0.0f;
        }
    }
    __syncthreads();

    // queries (2/thread): y_atom[n,h]
    for (int n = tid; n < N_MOL; n += NTHR) {
        float2 ae = g_mol2[h][n];
        float am = ae.x, eam = ae.y, t = -am;
        int b  = bin_of(t, mnv, inv);
        int s0 = sm.b.binStart[b], e0 = sm.b.binStart[b + 1];
        float acc = eam * sm.b.prefExp[b] + sm.b.sufVal[b + 1]
                  + (float)(P_PRO - e0) * (am + 1.0f);
        for (int i = s0; i < e0; i++) {
            float2 ve = sm.b.VE[i];
            acc += (ve.x <= t) ? eam * ve.y : (am + 1.0f + ve.x);
        }
        sm.b.rA[n] = acc;    // rA reused for y_atom
    }
    __syncthreads();

    // segment sum (16 threads per graph)
    {
        int gb = tid >> 4, q = tid & 15;
        int lo = 0, hi = N_MOL;
        while (lo < hi) { int m = (lo + hi) >> 1; if (sm.b.bs[m] < gb) lo = m + 1; else hi = m; }
        int s = lo;
        int l2 = lo, h2 = N_MOL;
        while (l2 < h2) { int m = (l2 + h2) >> 1; if (sm.b.bs[m] < gb + 1) l2 = m + 1; else h2 = m; }
        int span = l2 - s;
        int qlo = s + ((span * q) >> 4);
        int qhi = s + ((span * (q + 1)) >> 4);
        float p = 0.0f;
        for (int i = qlo; i < qhi; i++) p += sm.b.rA[i];
#pragma unroll
        for (int o = 8; o > 0; o >>= 1) p += __shfl_xor_sync(0xffffffffu, p, o);
        if (q == 0) g_ys[gb * HEADS + h] = p * 0.001f;
    }
    __threadfence();
    __syncthreads();
    if (bid != 0) {
        if (tid == 0) atomicAdd(&g_done, 1);
        return;
    }

    // ===== final MLP (block 0 after all 15 other consumers done) =====
    if (tid == 0) {
        while (atomicAdd(&g_done, 0) < HEADS - 1) {}
        atomicExch(&g_done, 0);
        __threadfence();
    }
    __syncthreads();
    float* ysF = sm.b.rE;    // dead; reuse for 64x16 ys
    if (tid < NGRAPH * HEADS) ysF[tid] = __ldcg(&g_ys[tid]);
    __syncthreads();
#pragma unroll
    for (int pass = 0; pass < 2; pass++) {
        int gb = (tid >> 5) + pass * 32;     // graph
        int j  = tid & 31;                   // hidden unit
        float a = b1[j];
#pragma unroll
        for (int hh = 0; hh < HEADS; hh++)
            a += ysF[gb * HEADS + hh] * W1[hh * (2 * HEADS) + j];
        float el = (a > 0.0f) ? a : (expf(a) - 1.0f);
        float c = el * W2[j];
#pragma unroll
        for (int o = 16; o > 0; o >>= 1) c += __shfl_xor_sync(0xffffffffu, c, o);
        if (j == 0) out[gb] = c + b2[0];
    }
}

// Inputs (metadata order):
// 0 mol_feats [2048,64] f32   1 fused_feats [2048,64] f32
// 2 Wmu [128,16] f32          3 bmu [16] f32
// 4 W1 [16,32] f32            5 b1 [32] f32
// 6 W2 [32,1] f32             7 b2 [1] f32
// 8 mol_batch [2048] int64-or-int32   9 num_graphs (static B=64)
extern "C" void kernel_launch(void* const* d_in, const int* in_sizes, int n_in,
                              void* d_out, int out_size) {
    fused_kernel<<<NBLK, NTHR>>>(
        (const float*)d_in[0], (const float*)d_in[1],
        (const float*)d_in[2], (const float*)d_in[3],
        (const float*)d_in[4], (const float*)d_in[5],
        (const float*)d_in[6], (const float*)d_in[7],
        (const int*)d_in[8], (float*)d_out);
}

// round 8
// speedup vs baseline: 1.5648x; 1.0934x over previous
#include <cuda_runtime.h>
#include <math.h>

#define N_MOL  2048
#define P_PRO  2048
#define HID    64
#define HEADS  16
#define NGRAPH 64
#define NB     512
#define NBLK   64           // 64 blocks x 1024 threads; blocks 0..15 are consumers
#define NTHR   1024

// ---- global scratch (no allocation allowed) ----
__device__ float2 g_mol2[HEADS][N_MOL];   // (a_mol, exp(a_mol))
__device__ float2 g_pro2[HEADS][P_PRO];   // (a_pro, exp(a_pro))
__device__ float  g_ys[NGRAPH * HEADS];
__device__ int    g_gen;                  // barrier generation (monotone)
__device__ int    g_count;                // barrier arrivals (self-resets)
__device__ int    g_done;                 // consumer completions (self-resets)

struct SA {                                // Phase A: 24,640 B
    float rows[64 * HID];                  // 16384
    float Ws[1024];                        // 4096
    float trans[HEADS][65];                // 4160
};
struct SB {                                // Phase B
    float2 VE[P_PRO];                      // 16384  (post-barrier)
    float  rA[P_PRO];                      // 8192   y_atom -> ysF (post-barrier)
    float  pad[32];                        // 128    => next field at 24704 > sizeof(SA)
    int    bs[N_MOL];                      // 8192   (PRE-barrier prep: beyond SA)
    int    hist[NB];                       // pre-barrier zeroed
    int    cnt[NB];                        // pre-barrier zeroed
    int    binStart[NB + 1];
    float  prefExp[NB];                    // sum exp over bins < k
    float  sufVal[NB + 1];                 // sum val over bins >= k
    float  sumVb[NB];                      // per-bin sum of values
    float  sumV2b[NB];                     // per-bin sum of squares
    float  redmn[32], redmx[32];
    int    iwarp[16];
    double dE[16], dV[16];
    float  mnv, mxv, invv, totE, totV;
    int    flag;
};
union SmemU { SA a; SB b; };

__device__ __forceinline__ int bin_of(float v, float mn, float inv) {
    // single shared helper => identical rounding for elements and queries
    int b = (int)(__fmul_rn(__fsub_rn(v, mn), inv));
    return b < 0 ? 0 : (b > NB - 1 ? NB - 1 : b);
}

__global__ __launch_bounds__(NTHR, 1)
void fused_kernel(const float* __restrict__ mol,
                  const float* __restrict__ pro,
                  const float* __restrict__ Wmu,
                  const float* __restrict__ bmu,
                  const float* __restrict__ W1,
                  const float* __restrict__ b1,
                  const float* __restrict__ W2,
                  const float* __restrict__ b2,
                  const int*   __restrict__ batch32,
                  float* __restrict__ out) {
    __shared__ SmemU sm;
    int tid  = threadIdx.x;
    int lane = tid & 31;
    int wrp  = tid >> 5;
    int bid  = blockIdx.x;

    // ===== Phase A: block bid projects 64 rows (all heads), one (row,head)/thread =====
    bool is_mol  = bid < 32;
    int  rowbase = (bid & 31) * 64;
    const float* srcbase = is_mol ? mol : pro;
    sm.a.Ws[tid] = Wmu[(is_mol ? 0 : 1024) + tid];
    ((float4*)sm.a.rows)[tid] = ((const float4*)(srcbase + rowbase * HID))[tid];
    __syncthreads();
    {
        int r = tid >> 4, h = tid & 15;
        float acc = is_mol ? bmu[h] : 0.0f;
#pragma unroll
        for (int k = 0; k < HID; k++)
            acc += sm.a.rows[r * HID + k] * sm.a.Ws[k * HEADS + h];
        sm.a.trans[h][r] = acc;
    }
    __syncthreads();
    {   // coalesced float2 writeout: 64 consecutive rows per 64-thread group
        int h2 = tid >> 6, r2 = tid & 63;
        float a = sm.a.trans[h2][r2];
        float2* dst = is_mol ? g_mol2[h2] : g_pro2[h2];
        dst[rowbase + r2] = make_float2(a, expf(a));
    }
    __threadfence();
    __syncthreads();

    // ===== barrier arrival (no spin yet) =====
    int my = 0;
    if (tid == 0) {
        my = *(volatile int*)&g_gen;
        if (atomicAdd(&g_count, 1) == NBLK - 1) {
            atomicExch(&g_count, 0);
            __threadfence();
            atomicAdd(&g_gen, 1);
        }
    }
    if (bid >= HEADS) return;

    // ===== consumer prep, overlapped with other blocks' Phase A =====
    for (int i = tid; i < N_MOL; i += NTHR) sm.b.bs[i] = batch32[i];
    if (tid < NB) { sm.b.hist[tid] = 0; sm.b.cnt[tid] = 0; }
    if (tid == 0) sm.b.flag = 0;
    __syncthreads();
    // int64 detection: sorted int32 word stream is monotone; int64's is not
    for (int i = tid; i < N_MOL - 1; i += NTHR)
        if (sm.b.bs[i] > sm.b.bs[i + 1]) sm.b.flag = 1;
    __syncthreads();
    if (sm.b.flag) {   // int64: low word of each element
        for (int i = tid; i < N_MOL; i += NTHR) sm.b.bs[i] = batch32[2 * i];
    }

    // ===== spin on barrier =====
    if (tid == 0) {
        while (*(volatile int*)&g_gen == my) {}
        __threadfence();
    }
    __syncthreads();

    // ===== Phase B: head h = bid, data register-resident =====
    int h = bid;
    float2 pA = g_pro2[h][tid];
    float2 pB = g_pro2[h][tid + 1024];
    float mn = fminf(pA.x, pB.x), mx = fmaxf(pA.x, pB.x);
#pragma unroll
    for (int o = 16; o > 0; o >>= 1) {
        mn = fminf(mn, __shfl_xor_sync(0xffffffffu, mn, o));
        mx = fmaxf(mx, __shfl_xor_sync(0xffffffffu, mx, o));
    }
    if (lane == 0) { sm.b.redmn[wrp] = mn; sm.b.redmx[wrp] = mx; }
    __syncthreads();
    if (wrp == 0) {
        float a = sm.b.redmn[lane], b = sm.b.redmx[lane];
#pragma unroll
        for (int o = 16; o > 0; o >>= 1) {
            a = fminf(a, __shfl_xor_sync(0xffffffffu, a, o));
            b = fmaxf(b, __shfl_xor_sync(0xffffffffu, b, o));
        }
        if (lane == 0) {
            sm.b.mnv = a; sm.b.mxv = b;
            sm.b.invv = (b > a) ? (float)NB / (b - a) : 0.0f;
        }
    }
    __syncthreads();
    float mnv = sm.b.mnv, mxv = sm.b.mxv, inv = sm.b.invv;

    // histogram straight from registers
    int bA = bin_of(pA.x, mnv, inv), bB = bin_of(pB.x, mnv, inv);
    atomicAdd(&sm.b.hist[bA], 1);
    atomicAdd(&sm.b.hist[bB], 1);
    __syncthreads();

    // exclusive scan of hist -> binStart (512 entries, 16 warps, shfl hierarchy)
    int myCnt = 0, myIncl = 0;
    {
        int s = 0;
        if (tid < NB) {
            myCnt = sm.b.hist[tid];
            s = myCnt;
#pragma unroll
            for (int o = 1; o < 32; o <<= 1) {
                int t = __shfl_up_sync(0xffffffffu, s, o);
                if (lane >= o) s += t;
            }
            if (lane == 31) sm.b.iwarp[wrp] = s;
        }
        __syncthreads();
        if (tid < 16) {
            int p = sm.b.iwarp[tid];
#pragma unroll
            for (int o = 1; o < 16; o <<= 1) {
                int t = __shfl_up_sync(0xffffu, p, o);
                if (tid >= o) p += t;
            }
            sm.b.iwarp[tid] = p;
        }
        __syncthreads();
        if (tid < NB) {
            myIncl = s + (wrp > 0 ? sm.b.iwarp[wrp - 1] : 0);
            sm.b.binStart[tid + 1] = myIncl;
            if (tid == 0) sm.b.binStart[0] = 0;
        }
    }
    __syncthreads();

    // scatter from registers
    {
        int pos = sm.b.binStart[bA] + atomicAdd(&sm.b.cnt[bA], 1);
        sm.b.VE[pos] = pA;
        pos = sm.b.binStart[bB] + atomicAdd(&sm.b.cnt[bB], 1);
        sm.b.VE[pos] = pB;
    }
    __syncthreads();

    // per-bin moments + joint double scan (prefExp exclusive / sufVal suffix)
    {
        double se = 0.0, sv = 0.0;
        if (tid < NB) {
            int s0 = myIncl - myCnt, e0 = myIncl;
            float fe = 0.0f, fv = 0.0f, fv2 = 0.0f;
            for (int i = s0; i < e0; i++) {
                float2 ve = sm.b.VE[i];
                fe += ve.y; fv += ve.x; fv2 += ve.x * ve.x;
            }
            sm.b.sumVb[tid]  = fv;
            sm.b.sumV2b[tid] = fv2;
            se = (double)fe; sv = (double)fv;
        }
        double ise = se, isv = sv;
        if (tid < NB) {
#pragma unroll
            for (int o = 1; o < 32; o <<= 1) {
                double te = __shfl_up_sync(0xffffffffu, ise, o);
                double tv = __shfl_up_sync(0xffffffffu, isv, o);
                if (lane >= o) { ise += te; isv += tv; }
            }
            if (lane == 31) { sm.b.dE[wrp] = ise; sm.b.dV[wrp] = isv; }
        }
        __syncthreads();
        if (tid < 16) {
            double pe = sm.b.dE[tid], pv = sm.b.dV[tid];
#pragma unroll
            for (int o = 1; o < 16; o <<= 1) {
                double te = __shfl_up_sync(0xffffu, pe, o);
                double tv = __shfl_up_sync(0xffffu, pv, o);
                if (tid >= o) { pe += te; pv += tv; }
            }
            sm.b.dE[tid] = pe; sm.b.dV[tid] = pv;
        }
        __syncthreads();
        if (tid < NB) {
            double offE = (wrp > 0) ? sm.b.dE[wrp - 1] : 0.0;
            double offV = (wrp > 0) ? sm.b.dV[wrp - 1] : 0.0;
            double inclE = ise + offE, inclV = isv + offV;
            double totalV = sm.b.dV[15];
            sm.b.prefExp[tid] = (float)(inclE - se);
            sm.b.sufVal[tid]  = (float)(totalV - (inclV - sv));
            if (tid == 0) {
                sm.b.sufVal[NB] = 0.0f;
                sm.b.totE = (float)sm.b.dE[15];
                sm.b.totV = (float)totalV;
            }
        }
    }
    __syncthreads();
    float totE = sm.b.totE, totV = sm.b.totV;

    // queries (2/thread): loop-free via bin-moment smoothing of the boundary bin
    for (int n = tid; n < N_MOL; n += NTHR) {
        float2 ae = g_mol2[h][n];
        float am = ae.x, eam = ae.y, t = -am;
        float acc;
        if (t >= mxv) {                     // all elements on exp side (exact)
            acc = eam * totE;
        } else if (t < mnv) {               // all elements on linear side (exact)
            acc = fmaf((float)P_PRO, am + 1.0f, totV);
        } else {
            int b  = bin_of(t, mnv, inv);
            int s0 = sm.b.binStart[b], e0 = sm.b.binStart[b + 1];
            float cb  = (float)(e0 - s0);
            float sV  = sm.b.sumVb[b];
            float sV2 = sm.b.sumV2b[b];
            float lin = am + 1.0f;
            // bins<b exact exp side; bins>b exact linear side; boundary bin:
            // sum of 1 + x + x^2/4 with x = am+v (|x| <= ~2*binwidth)
            acc = eam * sm.b.prefExp[b] + sm.b.sufVal[b + 1]
                + (float)(P_PRO - e0) * lin
                + cb * lin + sV
                + 0.25f * fmaf(cb, am * am, fmaf(2.0f * am, sV, sV2));
        }
        sm.b.rA[n] = acc;
    }
    __syncthreads();

    // segment sum (16 threads per graph)
    {
        int gb = tid >> 4, q = tid & 15;
        int lo = 0, hi = N_MOL;
        while (lo < hi) { int m = (lo + hi) >> 1; if (sm.b.bs[m] < gb) lo = m + 1; else hi = m; }
        int s = lo;
        int l2 = lo, h2 = N_MOL;
        while (l2 < h2) { int m = (l2 + h2) >> 1; if (sm.b.bs[m] < gb + 1) l2 = m + 1; else h2 = m; }
        int span = l2 - s;
        int qlo = s + ((span * q) >> 4);
        int qhi = s + ((span * (q + 1)) >> 4);
        float p = 0.0f;
        for (int i = qlo; i < qhi; i++) p += sm.b.rA[i];
#pragma unroll
        for (int o = 8; o > 0; o >>= 1) p += __shfl_xor_sync(0xffffffffu, p, o);
        if (q == 0) g_ys[gb * HEADS + h] = p * 0.001f;
    }
    __threadfence();
    __syncthreads();
    if (bid != 0) {
        if (tid == 0) atomicAdd(&g_done, 1);
        return;
    }

    // ===== final MLP (block 0 after all 15 other consumers done) =====
    if (tid == 0) {
        while (atomicAdd(&g_done, 0) < HEADS - 1) {}
        atomicExch(&g_done, 0);
        __threadfence();
    }
    __syncthreads();
    float* ysF = sm.b.rA;    // dead; reuse for 64x16 ys
    if (tid < NGRAPH * HEADS) ysF[tid] = __ldcg(&g_ys[tid]);
    __syncthreads();
#pragma unroll
    for (int pass = 0; pass < 2; pass++) {
        int gb = (tid >> 5) + pass * 32;     // graph
        int j  = tid & 31;                   // hidden unit
        float a = b1[j];
#pragma unroll
        for (int hh = 0; hh < HEADS; hh++)
            a += ysF[gb * HEADS + hh] * W1[hh * (2 * HEADS) + j];
        float el = (a > 0.0f) ? a : (expf(a) - 1.0f);
        float c = el * W2[j];
#pragma unroll
        for (int o = 16; o > 0; o >>= 1) c += __shfl_xor_sync(0xffffffffu, c, o);
        if (j == 0) out[gb] = c + b2[0];
    }
}

// Inputs (metadata order):
// 0 mol_feats [2048,64] f32   1 fused_feats [2048,64] f32
// 2 Wmu [128,16] f32          3 bmu [16] f32
// 4 W1 [16,32] f32            5 b1 [32] f32
// 6 W2 [32,1] f32             7 b2 [1] f32
// 8 mol_batch [2048] int64-or-int32   9 num_graphs (static B=64)
extern "C" void kernel_launch(void* const* d_in, const int* in_sizes, int n_in,
                              void* d_out, int out_size) {
    fused_kernel<<<NBLK, NTHR>>>(
        (const float*)d_in[0], (const float*)d_in[1],
        (const float*)d_in[2], (const float*)d_in[3],
        (const float*)d_in[4], (const float*)d_in[5],
        (const float*)d_in[6], (const float*)d_in[7],
        (const int*)d_in[8], (float*)d_out);
}